// round 14
// baseline (speedup 1.0000x reference)
#include <cuda_runtime.h>
#include <cstdint>

#define BATCH  4
#define N_SAMP 1024
#define N_PTS  16384
#define K_NEI  32
#define C_FEAT 128
#define CL     8                 // cluster size (CTAs per batch)
#define TPB    192               // w0-1: ball/gather, w2-5: FPS
#define NWARP_FPS 4
#define NWARP_BALL 2
#define PPT    16                // 2048 pts per CTA / 128 fps threads
#define NPAIR  (PPT / 2)
#define NSLOT  (CL * NWARP_FPS)  // 32 cluster-wide warp candidates
#define FULL   0xffffffffu
#define TX_BYTES (NSLOT * 16u)   // 32 producers x one v4 (16B)

// ---------------- f32x2 packed helpers (per-lane IEEE .rn == scalar; proven
// bit-exact on this bench: rel_err == 0.0) ----------------
__device__ __forceinline__ uint64_t pack2(float lo, float hi) {
    uint64_t r;
    asm("mov.b64 %0, {%1, %2};" : "=l"(r) : "f"(lo), "f"(hi));
    return r;
}
__device__ __forceinline__ void unpack2(uint64_t v, float& lo, float& hi) {
    asm("mov.b64 {%0, %1}, %2;" : "=f"(lo), "=f"(hi) : "l"(v));
}
__device__ __forceinline__ uint64_t add2(uint64_t a, uint64_t b) {
    uint64_t r;
    asm("add.rn.f32x2 %0, %1, %2;" : "=l"(r) : "l"(a), "l"(b));
    return r;
}
__device__ __forceinline__ uint64_t mul2(uint64_t a, uint64_t b) {
    uint64_t r;
    asm("mul.rn.f32x2 %0, %1, %2;" : "=l"(r) : "l"(a), "l"(b));
    return r;
}

// ---------------- threefry2x32 (JAX-compatible) ----------------
__device__ __forceinline__ uint32_t rotl32(uint32_t x, int r) {
    return (x << r) | (x >> (32 - r));
}
__device__ __forceinline__ void threefry2x32(uint32_t k0, uint32_t k1,
                                             uint32_t x0, uint32_t x1,
                                             uint32_t& o0, uint32_t& o1) {
    uint32_t ks2 = k0 ^ k1 ^ 0x1BD11BDAu;
    x0 += k0; x1 += k1;
#define TF_RND(r) { x0 += x1; x1 = rotl32(x1, (r)); x1 ^= x0; }
    TF_RND(13) TF_RND(15) TF_RND(26) TF_RND(6)   x0 += k1;  x1 += ks2 + 1u;
    TF_RND(17) TF_RND(29) TF_RND(16) TF_RND(24)  x0 += ks2; x1 += k0 + 2u;
    TF_RND(13) TF_RND(15) TF_RND(26) TF_RND(6)   x0 += k0;  x1 += k1 + 3u;
    TF_RND(17) TF_RND(29) TF_RND(16) TF_RND(24)  x0 += k1;  x1 += ks2 + 4u;
    TF_RND(13) TF_RND(15) TF_RND(26) TF_RND(6)   x0 += ks2; x1 += k0 + 5u;
#undef TF_RND
    o0 = x0; o1 = x1;
}
// start index for batch b (JAX threefry_partitionable=True path)
__device__ __forceinline__ int jax_start_idx(int b) {
    uint32_t k2a, k2b;
    threefry2x32(0u, 42u, 0u, 1u, k2a, k2b);
    uint32_t o0, o1;
    threefry2x32(k2a, k2b, 0u, (uint32_t)b, o0, o1);
    return (int)((o0 ^ o1) & (uint32_t)(N_PTS - 1));
}

// ---------------- cluster DSMEM / mbarrier / smem-sync helpers ----------------
__device__ __forceinline__ uint32_t mapa_peer(uint32_t laddr, uint32_t peer) {
    uint32_t r;
    asm volatile("mapa.shared::cluster.u32 %0, %1, %2;" : "=r"(r) : "r"(laddr), "r"(peer));
    return r;
}
__device__ __forceinline__ void st_async_raw_v4(uint32_t raddr, uint32_t rmbar,
                                                uint32_t a, uint32_t b,
                                                uint32_t c, uint32_t d) {
    asm volatile("st.async.shared::cluster.mbarrier::complete_tx::bytes.v4.b32 "
                 "[%0], {%1,%2,%3,%4}, [%5];"
                 :: "r"(raddr), "r"(a), "r"(b), "r"(c), "r"(d), "r"(rmbar) : "memory");
}
__device__ __forceinline__ void mbar_expect_tx(uint32_t mbar, uint32_t bytes) {
    asm volatile("mbarrier.arrive.expect_tx.shared.b64 _, [%0], %1;"
                 :: "r"(mbar), "r"(bytes) : "memory");
}
__device__ __forceinline__ void mbar_wait(uint32_t mbar, uint32_t phase) {
    uint32_t done = 0;
    while (!done) {
        asm volatile(
            "{\n\t.reg .pred p;\n\t"
            "mbarrier.try_wait.parity.acquire.cluster.shared::cta.b64 p, [%1], %2, 0x989680;\n\t"
            "selp.b32 %0, 1, 0, p;\n\t}"
            : "=r"(done) : "r"(mbar), "r"(phase) : "memory");
    }
}
__device__ __forceinline__ uint32_t ld_acquire_cta(uint32_t addr) {
    uint32_t v;
    asm volatile("ld.acquire.cta.shared::cta.b32 %0, [%1];" : "=r"(v) : "r"(addr) : "memory");
    return v;
}
__device__ __forceinline__ void st_release_cta(uint32_t addr, uint32_t v) {
    asm volatile("st.release.cta.shared::cta.b32 [%0], %1;" :: "r"(addr), "r"(v) : "memory");
}

// ---------------- fused FPS + ball + gather: one 8-CTA cluster per batch ----
// BLOCKED mapping (fps threads): fps-thread ft owns indices
//   [rank*2048 + ft*PPT, rank*2048 + (ft+1)*PPT)  -> index order == slot order,
// so every tie-break is ffs(ballot) and no index is ever transported.
__global__ void __cluster_dims__(CL, 1, 1) __launch_bounds__(TPB, 1)
fused_kernel(const float* __restrict__ xyz, const float* __restrict__ feat,
             float* __restrict__ out_xyz, float* __restrict__ out_feat) {
    const int b = blockIdx.x / CL;
    uint32_t rank;
    asm("mov.u32 %0, %%cluster_ctarank;" : "=r"(rank));
    const float* __restrict__ X = xyz + (size_t)b * N_PTS * 3;
    const int t = threadIdx.x;
    const int lane = t & 31, w = t >> 5;

    __shared__ uint4 s_q[2][NSLOT];           // cross-CTA candidates, dbl-buffered
    __shared__ unsigned long long s_mbar[2];
    __shared__ float4 s_ring[N_SAMP];         // published samples (x,y,z)
    __shared__ int    s_nb[NWARP_BALL][K_NEI];// per-ball-warp neighbor list
    __shared__ uint32_t s_cnt;                // samples available

    if (t == 0) {
        asm volatile("mbarrier.init.shared.b64 [%0], %1;"
                     :: "r"((uint32_t)__cvta_generic_to_shared(&s_mbar[0])), "r"(1) : "memory");
        asm volatile("mbarrier.init.shared.b64 [%0], %1;"
                     :: "r"((uint32_t)__cvta_generic_to_shared(&s_mbar[1])), "r"(1) : "memory");
        s_cnt = 0u;
    }
    __syncthreads();
    asm volatile("barrier.cluster.arrive.aligned;" ::: "memory");
    asm volatile("barrier.cluster.wait.aligned;" ::: "memory");

    const uint32_t cnt_addr = (uint32_t)__cvta_generic_to_shared(&s_cnt);

    if (w >= NWARP_BALL) {
        // ================= FPS warps (2-5; higher wid -> arbiter priority) ====
        const int ft = t - NWARP_BALL * 32;           // fps thread id 0..127
        const int wf = w - NWARP_BALL;                // fps warp 0..3
        const int tbase = (int)rank * 2048 + ft * PPT;

        float px[PPT], py[PPT], pz[PPT], md[PPT];
#pragma unroll
        for (int j = 0; j < PPT; j++) {
            const float* a = X + 3 * (tbase + j);
            px[j] = a[0]; py[j] = a[1]; pz[j] = a[2];
            md[j] = __int_as_float(0x7f800000);       // +inf
        }
        uint64_t px2[NPAIR], py2[NPAIR], pz2[NPAIR];
#pragma unroll
        for (int p = 0; p < NPAIR; p++) {
            px2[p] = pack2(px[2 * p], px[2 * p + 1]);
            py2[p] = pack2(py[2 * p], py[2 * p + 1]);
            pz2[p] = pack2(pz[2 * p], pz[2 * p + 1]);
        }

        // pre-resolve remote slot/mbar addresses for my warp's slot, both buffers
        const int myslot = (int)rank * NWARP_FPS + wf;
        uint32_t rs0[CL], rs1[CL], rm0[CL], rm1[CL];
        {
            uint32_t a0 = (uint32_t)__cvta_generic_to_shared(&s_q[0][myslot]);
            uint32_t a1 = (uint32_t)__cvta_generic_to_shared(&s_q[1][myslot]);
            uint32_t m0 = (uint32_t)__cvta_generic_to_shared(&s_mbar[0]);
            uint32_t m1 = (uint32_t)__cvta_generic_to_shared(&s_mbar[1]);
#pragma unroll
            for (int p = 0; p < CL; p++) {
                rs0[p] = mapa_peer(a0, (uint32_t)p);
                rs1[p] = mapa_peer(a1, (uint32_t)p);
                rm0[p] = mapa_peer(m0, (uint32_t)p);
                rm1[p] = mapa_peer(m1, (uint32_t)p);
            }
        }

        int cur = jax_start_idx(b);
        float qx = X[3 * cur + 0], qy = X[3 * cur + 1], qz = X[3 * cur + 2];
        if (t == 96) {   // w3 lane0: publish sample 0 to local ball warps
            s_ring[0] = make_float4(qx, qy, qz, 0.f);
            st_release_cta(cnt_addr, 1u);
        }

        for (int s = 0; ; s++) {
            if (rank == 0 && t == 128) {             // w4 lane0: output sample
                float* o = out_xyz + ((size_t)b * N_SAMP + s) * 3;
                o[0] = qx; o[1] = qy; o[2] = qz;
            }
            if (s == N_SAMP - 1) break;

            const int buf = s & 1;
            if (t == 64)                              // w2 lane0: arm phase mbar
                mbar_expect_tx((uint32_t)__cvta_generic_to_shared(&s_mbar[buf]), TX_BYTES);

            // ---- distance stage: packed f32x2 (EXACT: a-b==a+(-b), .rn, left-assoc) ----
            const uint64_t nqx2 = pack2(-qx, -qx);
            const uint64_t nqy2 = pack2(-qy, -qy);
            const uint64_t nqz2 = pack2(-qz, -qz);
            float m[PPT];
#pragma unroll
            for (int p = 0; p < NPAIR; p++) {
                uint64_t dx2 = add2(px2[p], nqx2);
                uint64_t dy2 = add2(py2[p], nqy2);
                uint64_t dz2 = add2(pz2[p], nqz2);
                uint64_t d2p = add2(add2(mul2(dx2, dx2), mul2(dy2, dy2)),
                                    mul2(dz2, dz2));
                float dlo, dhi;
                unpack2(d2p, dlo, dhi);
                float m0v = fminf(md[2 * p],     dlo);
                float m1v = fminf(md[2 * p + 1], dhi);
                md[2 * p] = m0v;  md[2 * p + 1] = m1v;
                m[2 * p]  = m0v;  m[2 * p + 1]  = m1v;
            }
            // ---- depth-4 argmax tree (left-priority => smallest j on ties) ----
            float tv[8], tx[8], ty[8], tz[8];
#pragma unroll
            for (int k = 0; k < 8; k++) {
                bool g = m[2 * k + 1] > m[2 * k];
                tv[k] = g ? m[2 * k + 1]  : m[2 * k];
                tx[k] = g ? px[2 * k + 1] : px[2 * k];
                ty[k] = g ? py[2 * k + 1] : py[2 * k];
                tz[k] = g ? pz[2 * k + 1] : pz[2 * k];
            }
#pragma unroll
            for (int n = 4; n >= 1; n >>= 1) {
#pragma unroll
                for (int k = 0; k < n; k++) {
                    bool g = tv[2 * k + 1] > tv[2 * k];
                    tv[k] = g ? tv[2 * k + 1] : tv[2 * k];
                    tx[k] = g ? tx[2 * k + 1] : tx[2 * k];
                    ty[k] = g ? ty[2 * k + 1] : ty[2 * k];
                    tz[k] = g ? tz[2 * k + 1] : tz[2 * k];
                }
            }
            const uint32_t bu = __float_as_uint(tv[0]);  // >=0: IEEE == u32 order

            // ---- warp argmax; winning lane broadcasts to all 8 CTAs ----
            uint32_t wm = __reduce_max_sync(FULL, bu);
            uint32_t mk = __ballot_sync(FULL, bu == wm);
            if (lane == __ffs(mk) - 1) {
                uint32_t cx = __float_as_uint(tx[0]);
                uint32_t cy = __float_as_uint(ty[0]);
                uint32_t cz = __float_as_uint(tz[0]);
                if (buf) {
#pragma unroll
                    for (int p = 0; p < CL; p++)
                        st_async_raw_v4(rs1[p], rm1[p], wm, cx, cy, cz);
                } else {
#pragma unroll
                    for (int p = 0; p < CL; p++)
                        st_async_raw_v4(rs0[p], rm0[p], wm, cx, cy, cz);
                }
            }

            // ---- wait + 1-slot-per-lane reduce; lowest winning slot wins ----
            mbar_wait((uint32_t)__cvta_generic_to_shared(&s_mbar[buf]),
                      (uint32_t)((s >> 1) & 1));
            uint4 dv = s_q[buf][lane];
            uint32_t gm = __reduce_max_sync(FULL, dv.x);
            uint32_t mk2 = __ballot_sync(FULL, dv.x == gm);
            int ws = __ffs(mk2) - 1;
            qx = __uint_as_float(__shfl_sync(FULL, dv.y, ws));
            qy = __uint_as_float(__shfl_sync(FULL, dv.z, ws));
            qz = __uint_as_float(__shfl_sync(FULL, dv.w, ws));

            if (t == 96) {  // w3 lane0: publish sample s+1
                s_ring[s + 1] = make_float4(qx, qy, qz, 0.f);
                st_release_cta(cnt_addr, (uint32_t)(s + 2));
            }
        }
    } else {
        // ================= ball+gather warps (0-1) ===========================
        const int wid16 = (int)rank * NWARP_BALL + w;  // 0..15 within batch
        const float4* __restrict__ F4 =
            (const float4*)(feat + (size_t)b * N_PTS * C_FEAT);
        const float R2 = 0.04f;  // f32(0.04): JAX weak-typed radius*radius
        for (int k = 0; k < N_SAMP / 16; k++) {
            const int s = k * 16 + wid16;
            while ((int)ld_acquire_cta(cnt_addr) <= s) __nanosleep(64);
            float4 q = s_ring[s];

            s_nb[w][lane] = -1;
            __syncwarp();
            int found = 0;
            for (int base = 0; base < N_PTS && found < K_NEI; base += 128) {
                float xs[4], ys[4], zs[4];
#pragma unroll
                for (int g = 0; g < 4; g++) {        // 12 LDGs in flight (MLP)
                    const float* a = X + 3 * (base + g * 32 + lane);
                    xs[g] = a[0]; ys[g] = a[1]; zs[g] = a[2];
                }
#pragma unroll
                for (int g = 0; g < 4; g++) {        // index-ordered groups
                    float dx = __fsub_rn(q.x, xs[g]);
                    float dy = __fsub_rn(q.y, ys[g]);
                    float dz = __fsub_rn(q.z, zs[g]);
                    float d2 = __fadd_rn(__fadd_rn(__fmul_rn(dx, dx),
                                                   __fmul_rn(dy, dy)),
                                         __fmul_rn(dz, dz));
                    bool in = d2 < R2;
                    unsigned mask = __ballot_sync(FULL, in);
                    if (in) {
                        int r = found + __popc(mask & ((1u << lane) - 1u));
                        if (r < K_NEI) s_nb[w][r] = base + g * 32 + lane;
                    }
                    found += __popc(mask);
                }
            }
            __syncwarp();
            // gather 32 feature rows (512B each), 4 rows in flight
            float4* dst = (float4*)(out_feat +
                           (((size_t)b * N_SAMP + s) * K_NEI) * C_FEAT);
#pragma unroll 1
            for (int k2 = 0; k2 < K_NEI; k2 += 4) {
                int r0 = s_nb[w][k2 + 0]; r0 = (r0 < 0) ? N_SAMP : r0;
                int r1 = s_nb[w][k2 + 1]; r1 = (r1 < 0) ? N_SAMP : r1;
                int r2 = s_nb[w][k2 + 2]; r2 = (r2 < 0) ? N_SAMP : r2;
                int r3 = s_nb[w][k2 + 3]; r3 = (r3 < 0) ? N_SAMP : r3;
                float4 v0 = F4[(size_t)r0 * 32 + lane];
                float4 v1 = F4[(size_t)r1 * 32 + lane];
                float4 v2 = F4[(size_t)r2 * 32 + lane];
                float4 v3 = F4[(size_t)r3 * 32 + lane];
                dst[(size_t)(k2 + 0) * 32 + lane] = v0;
                dst[(size_t)(k2 + 1) * 32 + lane] = v1;
                dst[(size_t)(k2 + 2) * 32 + lane] = v2;
                dst[(size_t)(k2 + 3) * 32 + lane] = v3;
            }
        }
    }

    // drain: no CTA exits while peers may still target its smem
    asm volatile("barrier.cluster.arrive.aligned;" ::: "memory");
    asm volatile("barrier.cluster.wait.aligned;" ::: "memory");
}

extern "C" void kernel_launch(void* const* d_in, const int* in_sizes, int n_in,
                              void* d_out, int out_size) {
    const float* xyz  = (const float*)d_in[0];
    const float* feat = (const float*)d_in[1];
    if (n_in >= 2 && in_sizes[0] != BATCH * N_PTS * 3) {  // defensive: by size
        xyz  = (const float*)d_in[1];
        feat = (const float*)d_in[0];
    }
    float* out = (float*)d_out;
    float* out_feat = out + (size_t)BATCH * N_SAMP * 3;

    fused_kernel<<<BATCH * CL, TPB>>>(xyz, feat, out, out_feat);
}

// round 15
// speedup vs baseline: 1.0242x; 1.0242x over previous
#include <cuda_runtime.h>
#include <cstdint>

#define BATCH  4
#define N_SAMP 1024
#define N_PTS  16384
#define K_NEI  32
#define C_FEAT 128
#define CL     8                 // cluster size (CTAs per batch)
#define TPB    256               // w0-3: ball/gather, w4-7: FPS
#define NWARP_FPS 4
#define NWARP_BALL 4
#define PPT    16                // 2048 pts per CTA / 128 fps threads
#define NPAIR  (PPT / 2)
#define NSLOT  (CL * NWARP_FPS)  // 32 cluster-wide warp candidates
#define FULL   0xffffffffu
#define TX_BYTES (NSLOT * 16u)   // 32 producers x one v4 (16B)

// SoA copy of xyz (built by transpose_kernel; device globals = no allocation)
__device__ float g_sx[BATCH * N_PTS];
__device__ float g_sy[BATCH * N_PTS];
__device__ float g_sz[BATCH * N_PTS];

// ---------------- f32x2 packed helpers (per-lane IEEE .rn == scalar; proven
// bit-exact on this bench: rel_err == 0.0) ----------------
__device__ __forceinline__ uint64_t pack2(float lo, float hi) {
    uint64_t r;
    asm("mov.b64 %0, {%1, %2};" : "=l"(r) : "f"(lo), "f"(hi));
    return r;
}
__device__ __forceinline__ void unpack2(uint64_t v, float& lo, float& hi) {
    asm("mov.b64 {%0, %1}, %2;" : "=f"(lo), "=f"(hi) : "l"(v));
}
__device__ __forceinline__ uint64_t add2(uint64_t a, uint64_t b) {
    uint64_t r;
    asm("add.rn.f32x2 %0, %1, %2;" : "=l"(r) : "l"(a), "l"(b));
    return r;
}
__device__ __forceinline__ uint64_t mul2(uint64_t a, uint64_t b) {
    uint64_t r;
    asm("mul.rn.f32x2 %0, %1, %2;" : "=l"(r) : "l"(a), "l"(b));
    return r;
}

// ---------------- threefry2x32 (JAX-compatible) ----------------
__device__ __forceinline__ uint32_t rotl32(uint32_t x, int r) {
    return (x << r) | (x >> (32 - r));
}
__device__ __forceinline__ void threefry2x32(uint32_t k0, uint32_t k1,
                                             uint32_t x0, uint32_t x1,
                                             uint32_t& o0, uint32_t& o1) {
    uint32_t ks2 = k0 ^ k1 ^ 0x1BD11BDAu;
    x0 += k0; x1 += k1;
#define TF_RND(r) { x0 += x1; x1 = rotl32(x1, (r)); x1 ^= x0; }
    TF_RND(13) TF_RND(15) TF_RND(26) TF_RND(6)   x0 += k1;  x1 += ks2 + 1u;
    TF_RND(17) TF_RND(29) TF_RND(16) TF_RND(24)  x0 += ks2; x1 += k0 + 2u;
    TF_RND(13) TF_RND(15) TF_RND(26) TF_RND(6)   x0 += k0;  x1 += k1 + 3u;
    TF_RND(17) TF_RND(29) TF_RND(16) TF_RND(24)  x0 += k1;  x1 += ks2 + 4u;
    TF_RND(13) TF_RND(15) TF_RND(26) TF_RND(6)   x0 += ks2; x1 += k0 + 5u;
#undef TF_RND
    o0 = x0; o1 = x1;
}
// start index for batch b (JAX threefry_partitionable=True path)
__device__ __forceinline__ int jax_start_idx(int b) {
    uint32_t k2a, k2b;
    threefry2x32(0u, 42u, 0u, 1u, k2a, k2b);
    uint32_t o0, o1;
    threefry2x32(k2a, k2b, 0u, (uint32_t)b, o0, o1);
    return (int)((o0 ^ o1) & (uint32_t)(N_PTS - 1));
}

// ---------------- cluster DSMEM / mbarrier / smem-sync helpers ----------------
__device__ __forceinline__ uint32_t mapa_peer(uint32_t laddr, uint32_t peer) {
    uint32_t r;
    asm volatile("mapa.shared::cluster.u32 %0, %1, %2;" : "=r"(r) : "r"(laddr), "r"(peer));
    return r;
}
__device__ __forceinline__ void st_async_raw_v4(uint32_t raddr, uint32_t rmbar,
                                                uint32_t a, uint32_t b,
                                                uint32_t c, uint32_t d) {
    asm volatile("st.async.shared::cluster.mbarrier::complete_tx::bytes.v4.b32 "
                 "[%0], {%1,%2,%3,%4}, [%5];"
                 :: "r"(raddr), "r"(a), "r"(b), "r"(c), "r"(d), "r"(rmbar) : "memory");
}
__device__ __forceinline__ void mbar_expect_tx(uint32_t mbar, uint32_t bytes) {
    asm volatile("mbarrier.arrive.expect_tx.shared.b64 _, [%0], %1;"
                 :: "r"(mbar), "r"(bytes) : "memory");
}
__device__ __forceinline__ void mbar_wait(uint32_t mbar, uint32_t phase) {
    uint32_t done = 0;
    while (!done) {
        asm volatile(
            "{\n\t.reg .pred p;\n\t"
            "mbarrier.try_wait.parity.acquire.cluster.shared::cta.b64 p, [%1], %2, 0x989680;\n\t"
            "selp.b32 %0, 1, 0, p;\n\t}"
            : "=r"(done) : "r"(mbar), "r"(phase) : "memory");
    }
}
__device__ __forceinline__ uint32_t ld_acquire_cta(uint32_t addr) {
    uint32_t v;
    asm volatile("ld.acquire.cta.shared::cta.b32 %0, [%1];" : "=r"(v) : "r"(addr) : "memory");
    return v;
}
__device__ __forceinline__ void st_release_cta(uint32_t addr, uint32_t v) {
    asm volatile("st.release.cta.shared::cta.b32 [%0], %1;" :: "r"(addr), "r"(v) : "memory");
}

// ---------------- AoS -> SoA transpose (runs before fused kernel) ----------
__global__ void transpose_kernel(const float* __restrict__ xyz) {
    int i = blockIdx.x * blockDim.x + threadIdx.x;
    if (i < BATCH * N_PTS) {
        const float* a = xyz + 3 * (size_t)i;
        g_sx[i] = a[0];
        g_sy[i] = a[1];
        g_sz[i] = a[2];
    }
}

// ---------------- fused FPS + ball + gather: one 8-CTA cluster per batch ----
// BLOCKED mapping (fps threads): fps-thread ft owns indices
//   [rank*2048 + ft*PPT, rank*2048 + (ft+1)*PPT)  -> index order == slot order,
// so every tie-break is ffs(ballot) and no index is ever transported.
__global__ void __cluster_dims__(CL, 1, 1) __launch_bounds__(TPB, 1)
fused_kernel(const float* __restrict__ xyz, const float* __restrict__ feat,
             float* __restrict__ out_xyz, float* __restrict__ out_feat) {
    const int b = blockIdx.x / CL;
    uint32_t rank;
    asm("mov.u32 %0, %%cluster_ctarank;" : "=r"(rank));
    const float* __restrict__ X = xyz + (size_t)b * N_PTS * 3;
    const int t = threadIdx.x;
    const int lane = t & 31, w = t >> 5;

    __shared__ uint4 s_q[2][NSLOT];           // cross-CTA candidates, dbl-buffered
    __shared__ unsigned long long s_mbar[2];
    __shared__ float4 s_ring[N_SAMP];         // published samples (x,y,z)
    __shared__ int    s_nb[NWARP_BALL][K_NEI];// per-ball-warp neighbor list
    __shared__ uint32_t s_cnt;                // samples available

    if (t == 0) {
        asm volatile("mbarrier.init.shared.b64 [%0], %1;"
                     :: "r"((uint32_t)__cvta_generic_to_shared(&s_mbar[0])), "r"(1) : "memory");
        asm volatile("mbarrier.init.shared.b64 [%0], %1;"
                     :: "r"((uint32_t)__cvta_generic_to_shared(&s_mbar[1])), "r"(1) : "memory");
        s_cnt = 0u;
    }
    __syncthreads();
    asm volatile("barrier.cluster.arrive.aligned;" ::: "memory");
    asm volatile("barrier.cluster.wait.aligned;" ::: "memory");

    const uint32_t cnt_addr = (uint32_t)__cvta_generic_to_shared(&s_cnt);

    if (w >= NWARP_BALL) {
        // ================= FPS warps (4-7; higher wid -> arbiter priority) ====
        const int ft = t - NWARP_BALL * 32;           // fps thread id 0..127
        const int wf = w - NWARP_BALL;                // fps warp 0..3
        const int tbase = (int)rank * 2048 + ft * PPT;

        float px[PPT], py[PPT], pz[PPT], md[PPT];
#pragma unroll
        for (int j = 0; j < PPT; j++) {
            const float* a = X + 3 * (tbase + j);
            px[j] = a[0]; py[j] = a[1]; pz[j] = a[2];
            md[j] = __int_as_float(0x7f800000);       // +inf
        }
        uint64_t px2[NPAIR], py2[NPAIR], pz2[NPAIR];
#pragma unroll
        for (int p = 0; p < NPAIR; p++) {
            px2[p] = pack2(px[2 * p], px[2 * p + 1]);
            py2[p] = pack2(py[2 * p], py[2 * p + 1]);
            pz2[p] = pack2(pz[2 * p], pz[2 * p + 1]);
        }

        // pre-resolve remote slot/mbar addresses for my warp's slot, both buffers
        const int myslot = (int)rank * NWARP_FPS + wf;
        uint32_t rs0[CL], rs1[CL], rm0[CL], rm1[CL];
        {
            uint32_t a0 = (uint32_t)__cvta_generic_to_shared(&s_q[0][myslot]);
            uint32_t a1 = (uint32_t)__cvta_generic_to_shared(&s_q[1][myslot]);
            uint32_t m0 = (uint32_t)__cvta_generic_to_shared(&s_mbar[0]);
            uint32_t m1 = (uint32_t)__cvta_generic_to_shared(&s_mbar[1]);
#pragma unroll
            for (int p = 0; p < CL; p++) {
                rs0[p] = mapa_peer(a0, (uint32_t)p);
                rs1[p] = mapa_peer(a1, (uint32_t)p);
                rm0[p] = mapa_peer(m0, (uint32_t)p);
                rm1[p] = mapa_peer(m1, (uint32_t)p);
            }
        }

        int cur = jax_start_idx(b);
        float qx = X[3 * cur + 0], qy = X[3 * cur + 1], qz = X[3 * cur + 2];
        if (t == 160) {   // w5 lane0: publish sample 0 to local ball warps
            s_ring[0] = make_float4(qx, qy, qz, 0.f);
            st_release_cta(cnt_addr, 1u);
        }

        for (int s = 0; ; s++) {
            if (rank == 0 && t == 192) {             // w6 lane0: output sample
                float* o = out_xyz + ((size_t)b * N_SAMP + s) * 3;
                o[0] = qx; o[1] = qy; o[2] = qz;
            }
            if (s == N_SAMP - 1) break;

            const int buf = s & 1;
            if (t == 128)                             // w4 lane0: arm phase mbar
                mbar_expect_tx((uint32_t)__cvta_generic_to_shared(&s_mbar[buf]), TX_BYTES);

            // ---- distance stage: packed f32x2 (EXACT: a-b==a+(-b), .rn, left-assoc) ----
            const uint64_t nqx2 = pack2(-qx, -qx);
            const uint64_t nqy2 = pack2(-qy, -qy);
            const uint64_t nqz2 = pack2(-qz, -qz);
            float m[PPT];
#pragma unroll
            for (int p = 0; p < NPAIR; p++) {
                uint64_t dx2 = add2(px2[p], nqx2);
                uint64_t dy2 = add2(py2[p], nqy2);
                uint64_t dz2 = add2(pz2[p], nqz2);
                uint64_t d2p = add2(add2(mul2(dx2, dx2), mul2(dy2, dy2)),
                                    mul2(dz2, dz2));
                float dlo, dhi;
                unpack2(d2p, dlo, dhi);
                float m0v = fminf(md[2 * p],     dlo);
                float m1v = fminf(md[2 * p + 1], dhi);
                md[2 * p] = m0v;  md[2 * p + 1] = m1v;
                m[2 * p]  = m0v;  m[2 * p + 1]  = m1v;
            }
            // ---- depth-4 argmax tree (left-priority => smallest j on ties) ----
            float tv[8], tx[8], ty[8], tz[8];
#pragma unroll
            for (int k = 0; k < 8; k++) {
                bool g = m[2 * k + 1] > m[2 * k];
                tv[k] = g ? m[2 * k + 1]  : m[2 * k];
                tx[k] = g ? px[2 * k + 1] : px[2 * k];
                ty[k] = g ? py[2 * k + 1] : py[2 * k];
                tz[k] = g ? pz[2 * k + 1] : pz[2 * k];
            }
#pragma unroll
            for (int n = 4; n >= 1; n >>= 1) {
#pragma unroll
                for (int k = 0; k < n; k++) {
                    bool g = tv[2 * k + 1] > tv[2 * k];
                    tv[k] = g ? tv[2 * k + 1] : tv[2 * k];
                    tx[k] = g ? tx[2 * k + 1] : tx[2 * k];
                    ty[k] = g ? ty[2 * k + 1] : ty[2 * k];
                    tz[k] = g ? tz[2 * k + 1] : tz[2 * k];
                }
            }
            const uint32_t bu = __float_as_uint(tv[0]);  // >=0: IEEE == u32 order

            // ---- warp argmax; winning lane broadcasts to all 8 CTAs ----
            uint32_t wm = __reduce_max_sync(FULL, bu);
            uint32_t mk = __ballot_sync(FULL, bu == wm);
            if (lane == __ffs(mk) - 1) {
                uint32_t cx = __float_as_uint(tx[0]);
                uint32_t cy = __float_as_uint(ty[0]);
                uint32_t cz = __float_as_uint(tz[0]);
                if (buf) {
#pragma unroll
                    for (int p = 0; p < CL; p++)
                        st_async_raw_v4(rs1[p], rm1[p], wm, cx, cy, cz);
                } else {
#pragma unroll
                    for (int p = 0; p < CL; p++)
                        st_async_raw_v4(rs0[p], rm0[p], wm, cx, cy, cz);
                }
            }

            // ---- wait + 1-slot-per-lane reduce; lowest winning slot wins ----
            mbar_wait((uint32_t)__cvta_generic_to_shared(&s_mbar[buf]),
                      (uint32_t)((s >> 1) & 1));
            uint4 dv = s_q[buf][lane];
            uint32_t gm = __reduce_max_sync(FULL, dv.x);
            uint32_t mk2 = __ballot_sync(FULL, dv.x == gm);
            int ws = __ffs(mk2) - 1;
            qx = __uint_as_float(__shfl_sync(FULL, dv.y, ws));
            qy = __uint_as_float(__shfl_sync(FULL, dv.z, ws));
            qz = __uint_as_float(__shfl_sync(FULL, dv.w, ws));

            if (t == 160) {  // w5 lane0: publish sample s+1
                s_ring[s + 1] = make_float4(qx, qy, qz, 0.f);
                st_release_cta(cnt_addr, (uint32_t)(s + 2));
            }
        }
    } else {
        // ================= ball+gather warps (0-3) ===========================
        const int wid32 = (int)rank * NWARP_BALL + w;  // 0..31 within batch
        const float4* __restrict__ F4 =
            (const float4*)(feat + (size_t)b * N_PTS * C_FEAT);
        const float* __restrict__ SX = g_sx + (size_t)b * N_PTS;
        const float* __restrict__ SY = g_sy + (size_t)b * N_PTS;
        const float* __restrict__ SZ = g_sz + (size_t)b * N_PTS;
        const float R2 = 0.04f;  // f32(0.04): JAX weak-typed radius*radius
        for (int k = 0; k < N_SAMP / 32; k++) {
            const int s = k * 32 + wid32;
            while ((int)ld_acquire_cta(cnt_addr) <= s) __nanosleep(64);
            float4 q = s_ring[s];

            s_nb[w][lane] = -1;
            __syncwarp();
            int found = 0;
            for (int base = 0; base < N_PTS && found < K_NEI; base += 128) {
                float xs[4], ys[4], zs[4];
#pragma unroll
                for (int g = 0; g < 4; g++) {        // SoA: 1 line per LDG
                    xs[g] = SX[base + g * 32 + lane];
                    ys[g] = SY[base + g * 32 + lane];
                    zs[g] = SZ[base + g * 32 + lane];
                }
#pragma unroll
                for (int g = 0; g < 4; g++) {        // index-ordered groups
                    float dx = __fsub_rn(q.x, xs[g]);
                    float dy = __fsub_rn(q.y, ys[g]);
                    float dz = __fsub_rn(q.z, zs[g]);
                    float d2 = __fadd_rn(__fadd_rn(__fmul_rn(dx, dx),
                                                   __fmul_rn(dy, dy)),
                                         __fmul_rn(dz, dz));
                    bool in = d2 < R2;
                    unsigned mask = __ballot_sync(FULL, in);
                    if (in) {
                        int r = found + __popc(mask & ((1u << lane) - 1u));
                        if (r < K_NEI) s_nb[w][r] = base + g * 32 + lane;
                    }
                    found += __popc(mask);
                }
            }
            __syncwarp();
            // gather 32 feature rows (512B each), 4 rows in flight
            float4* dst = (float4*)(out_feat +
                           (((size_t)b * N_SAMP + s) * K_NEI) * C_FEAT);
#pragma unroll 1
            for (int k2 = 0; k2 < K_NEI; k2 += 4) {
                int r0 = s_nb[w][k2 + 0]; r0 = (r0 < 0) ? N_SAMP : r0;
                int r1 = s_nb[w][k2 + 1]; r1 = (r1 < 0) ? N_SAMP : r1;
                int r2 = s_nb[w][k2 + 2]; r2 = (r2 < 0) ? N_SAMP : r2;
                int r3 = s_nb[w][k2 + 3]; r3 = (r3 < 0) ? N_SAMP : r3;
                float4 v0 = F4[(size_t)r0 * 32 + lane];
                float4 v1 = F4[(size_t)r1 * 32 + lane];
                float4 v2 = F4[(size_t)r2 * 32 + lane];
                float4 v3 = F4[(size_t)r3 * 32 + lane];
                dst[(size_t)(k2 + 0) * 32 + lane] = v0;
                dst[(size_t)(k2 + 1) * 32 + lane] = v1;
                dst[(size_t)(k2 + 2) * 32 + lane] = v2;
                dst[(size_t)(k2 + 3) * 32 + lane] = v3;
            }
        }
    }

    // drain: no CTA exits while peers may still target its smem
    asm volatile("barrier.cluster.arrive.aligned;" ::: "memory");
    asm volatile("barrier.cluster.wait.aligned;" ::: "memory");
}

extern "C" void kernel_launch(void* const* d_in, const int* in_sizes, int n_in,
                              void* d_out, int out_size) {
    const float* xyz  = (const float*)d_in[0];
    const float* feat = (const float*)d_in[1];
    if (n_in >= 2 && in_sizes[0] != BATCH * N_PTS * 3) {  // defensive: by size
        xyz  = (const float*)d_in[1];
        feat = (const float*)d_in[0];
    }
    float* out = (float*)d_out;
    float* out_feat = out + (size_t)BATCH * N_SAMP * 3;

    transpose_kernel<<<(BATCH * N_PTS + 255) / 256, 256>>>(xyz);
    fused_kernel<<<BATCH * CL, TPB>>>(xyz, feat, out, out_feat);
}